// round 15
// baseline (speedup 1.0000x reference)
#include <cuda_runtime.h>
#include <cuda_fp16.h>
#include <math.h>
#include <stdint.h>

#define NTOK 8192
#define DIM  1024
#define NEXP 8
#define HID  4096
#define CAP  1024

// ================= scratch =================
__device__ __half g_xf[(size_t)NTOK * DIM];
__device__ __half g_hf[(size_t)NTOK * HID];
__device__ __half g_w1f[(size_t)NEXP * HID * DIM];  // transposed [E][H][D]
__device__ __half g_w2f[(size_t)NEXP * DIM * HID];  // transposed [E][D][H]
__device__ float g_probs[(size_t)NTOK * NEXP];
__device__ float g_lse2[NTOK];
__device__ float g_eprob[NTOK];
__device__ float g_oscale[NTOK];
__device__ int   g_eidx[NTOK];
__device__ int   g_slot[NTOK];
__device__ int   g_sortidx[NTOK];
__device__ int   g_tok_of_slot[NEXP * CAP];
__device__ int   g_counts[NEXP];

__device__ __forceinline__ uint32_t smem_u32(const void* p) {
    uint32_t a;
    asm("{ .reg .u64 t; cvta.to.shared.u64 t, %1; cvt.u32.u64 %0, t; }" : "=r"(a) : "l"(p));
    return a;
}
__device__ __forceinline__ uint32_t pack_h2(float a, float b) {
    __half2 h = __floats2half2_rn(a, b);
    return *(uint32_t*)&h;
}

// ---- PTX: mma / ldmatrix / cp.async ----
__device__ __forceinline__ void mma16816(float* c, const uint32_t* a, const uint32_t* b) {
    asm volatile("mma.sync.aligned.m16n8k16.row.col.f32.f16.f16.f32 "
                 "{%0,%1,%2,%3}, {%4,%5,%6,%7}, {%8,%9}, {%0,%1,%2,%3};"
                 : "+f"(c[0]), "+f"(c[1]), "+f"(c[2]), "+f"(c[3])
                 : "r"(a[0]), "r"(a[1]), "r"(a[2]), "r"(a[3]), "r"(b[0]), "r"(b[1]));
}
#define LDSM4(r0, r1, r2, r3, a) \
    asm volatile("ldmatrix.sync.aligned.m8n8.x4.shared.b16 {%0,%1,%2,%3}, [%4];" \
                 : "=r"(r0), "=r"(r1), "=r"(r2), "=r"(r3) : "r"(a))
__device__ __forceinline__ void cp_async16(uint32_t saddr, const void* gptr) {
    asm volatile("cp.async.cg.shared.global [%0], [%1], 16;" :: "r"(saddr), "l"(gptr));
}
#define CP_COMMIT() asm volatile("cp.async.commit_group;" ::: "memory")
#define CP_WAIT1()  asm volatile("cp.async.wait_group 1;" ::: "memory")

__device__ __forceinline__ uint32_t swz(uint32_t off) { return off ^ ((off >> 3) & 0x70); }

// ================= fused prep: router (blocks 0..255) + weight transconv =================
__global__ __launch_bounds__(256) void prep_kernel(
    const float* __restrict__ x, const float* __restrict__ Wg,
    const float* __restrict__ W1, const float* __restrict__ W2,
    __half* __restrict__ w1f, __half* __restrict__ w2f)
{
    __shared__ float sh[8192];
    const int bid = blockIdx.x;
    const int tid = threadIdx.x;

    if (bid < 256) {
        // ---- router ----
#pragma unroll
        for (int k = 0; k < 32; k++) {
            int j = k * 256 + tid;
            sh[(j & 7) * 1024 + (j >> 3)] = Wg[j];   // sWg[e][d]
        }
        __syncthreads();
        const int warp = tid >> 5, lane = tid & 31;
#pragma unroll 1
        for (int it = 0; it < 4; it++) {
            int n = bid * 32 + it * 8 + warp;
            const float* xr = x + (size_t)n * DIM;
            float acc[NEXP];
#pragma unroll
            for (int e = 0; e < NEXP; e++) acc[e] = 0.f;
#pragma unroll 8
            for (int i = 0; i < 32; i++) {
                int d = lane + i * 32;
                float xv = xr[d];
#pragma unroll
                for (int e = 0; e < NEXP; e++) acc[e] += xv * sh[e * 1024 + d];
            }
#pragma unroll
            for (int e = 0; e < NEXP; e++) {
#pragma unroll
                for (int o = 16; o > 0; o >>= 1)
                    acc[e] += __shfl_xor_sync(0xffffffffu, acc[e], o);
            }
            if (lane == 0) {
                float m = acc[0]; int bi = 0;
#pragma unroll
                for (int e = 1; e < NEXP; e++) if (acc[e] > m) { m = acc[e]; bi = e; }
                float p[NEXP], s = 0.f;
#pragma unroll
                for (int e = 0; e < NEXP; e++) { p[e] = expf(acc[e] - m); s += p[e]; }
                float inv = 1.f / s;
#pragma unroll
                for (int e = 0; e < NEXP; e++) {
                    p[e] *= inv;
                    g_probs[(size_t)n * NEXP + e] = p[e];
                }
                float lse = m + logf(s);
                g_lse2[n] = lse * lse;
                g_eidx[n] = bi;
                g_eprob[n] = p[bi];
                atomicAdd(&g_counts[bi], 1);
            }
        }
    } else {
        // ---- weight transpose + fp16 convert, 64x64 tiles ----
        int b = bid - 256;
        const float* src; __half* dst; int K, N;
        if (b < 8192) { src = W1; dst = w1f; K = DIM; N = HID; }
        else { b -= 8192; src = W2; dst = w2f; K = HID; N = DIM; }
        int e = b >> 10;
        int rem = b & 1023;
        int tiles_n = N >> 6;
        int nx = rem % tiles_n, ky = rem / tiles_n;
        const float* s = src + (size_t)e * K * N;
        __half* o = dst + (size_t)e * N * K;
        int n0 = nx * 64, k0 = ky * 64;
#pragma unroll
        for (int i = 0; i < 16; i++) {
            int lin = i * 256 + tid;
            int kr = lin >> 6, nc = lin & 63;
            sh[kr * 65 + nc] = s[(size_t)(k0 + kr) * N + n0 + nc];
        }
        __syncthreads();
        int r = tid >> 2, c4 = tid & 3;
        uint32_t w[8];
#pragma unroll
        for (int j = 0; j < 8; j++) {
            float a = sh[(c4 * 16 + 2 * j) * 65 + r];
            float bb = sh[(c4 * 16 + 2 * j + 1) * 65 + r];
            w[j] = pack_h2(a, bb);
        }
        uint4* dp = (uint4*)(o + (size_t)(n0 + r) * K + k0 + c4 * 16);
        dp[0] = make_uint4(w[0], w[1], w[2], w[3]);
        dp[1] = make_uint4(w[4], w[5], w[6], w[7]);
    }
}

// ================= fused pos (blocks 0..7) + reduce (block 8) =================
__global__ __launch_bounds__(1024) void pos_reduce_kernel(float* aux_out) {
    const int tid = threadIdx.x;
    if (blockIdx.x < 8) {
        const int e = blockIdx.x;
        const int lane = tid & 31, wid = tid >> 5;
        __shared__ int wsum[32], wbase[32], sbase;
        int st = 0;
        for (int j = 0; j < e; j++) st += g_counts[j];
        if (tid == 0) sbase = 0;
        __syncthreads();
        for (int n0 = 0; n0 < NTOK; n0 += 1024) {
            int n = n0 + tid;
            bool pred = (g_eidx[n] == e);
            unsigned b = __ballot_sync(0xffffffffu, pred);
            int wpre = __popc(b & ((1u << lane) - 1u));
            if (lane == 0) wsum[wid] = __popc(b);
            __syncthreads();
            if (tid == 0) {
                int r = sbase;
#pragma unroll
                for (int w = 0; w < 32; w++) { wbase[w] = r; r += wsum[w]; }
                sbase = r;
            }
            __syncthreads();
            if (pred) {
                int pos = wbase[wid] + wpre;
                g_sortidx[st + pos] = n;
                if (pos < CAP) { g_slot[n] = pos; g_tok_of_slot[e * CAP + pos] = n; }
                else g_slot[n] = -1;
            }
            __syncthreads();
        }
    } else {
        __shared__ float sz[1024];
        __shared__ float sp[NEXP][1024];
        float z = 0.f, p[NEXP];
#pragma unroll
        for (int e = 0; e < NEXP; e++) p[e] = 0.f;
        for (int n = tid; n < NTOK; n += 1024) {
            z += g_lse2[n];
#pragma unroll
            for (int e = 0; e < NEXP; e++) p[e] += g_probs[(size_t)n * NEXP + e];
        }
        sz[tid] = z;
#pragma unroll
        for (int e = 0; e < NEXP; e++) sp[e][tid] = p[e];
        __syncthreads();
        for (int off = 512; off > 0; off >>= 1) {
            if (tid < off) {
                sz[tid] += sz[tid + off];
#pragma unroll
                for (int e = 0; e < NEXP; e++) sp[e][tid] += sp[e][tid + off];
            }
            __syncthreads();
        }
        if (tid == 0) {
            float zloss = sz[0] / (float)NTOK;
            float dot = 0.f;
#pragma unroll
            for (int e = 0; e < NEXP; e++) {
                float fi = (float)g_counts[e] / (float)NTOK;
                float pi = sp[e][0] / (float)NTOK;
                dot += fi * pi;
            }
            if (aux_out) *aux_out = 0.01f * (float)NEXP * dot + 0.001f * zloss;
        }
    }
}

// ================= fused gather (blocks 0..8191) + oscale (8192..8255) =================
__global__ __launch_bounds__(128) void gather_kernel(const float* __restrict__ x) {
    int bid = blockIdx.x;
    if (bid < NEXP * CAP) {
        int e = bid >> 10;
        int slot = bid & (CAP - 1);
        if (slot >= min(g_counts[e], CAP)) return;
        int n = g_tok_of_slot[bid];
        const float4* src = (const float4*)(x + (size_t)n * DIM);
        uint2* dst = (uint2*)(g_xf + (size_t)bid * DIM);
#pragma unroll
        for (int q = 0; q < 2; q++) {
            int i = q * 128 + threadIdx.x;
            float4 v = src[i];
            dst[i] = make_uint2(pack_h2(v.x, v.y), pack_h2(v.z, v.w));
        }
    } else {
        int n = (bid - NEXP * CAP) * 128 + threadIdx.x;
        g_oscale[n] = g_eprob[g_sortidx[n]];
    }
}

// ====== fp16 HMMA grouped GEMM: CTA 128x128, 4 warps (64x64 warp tile), BK=64, 3 stages ======
#define OFF_A  0u
#define OFF_B  16384u
#define ST_SZ  32768u
#define GEMM_SMEM (3u * ST_SZ)

// MODE 0: GELU epilogue -> fp16 hidden; MODE 1: final -> out[token] * oscale
template <int MODE, int K, int NTOT>
__global__ __launch_bounds__(128, 2) void gemm_kernel(
    const __half* __restrict__ Ag, const __half* __restrict__ Bg,
    const float* __restrict__ bias_g,
    __half* __restrict__ outh, float* __restrict__ outf)
{
    extern __shared__ __align__(128) char smem[];
    const uint32_t sbase = smem_u32(smem);
    const int tid  = threadIdx.x;
    const int wid  = tid >> 5;
    const int lane = tid & 31;
    const int wm   = wid & 1;            // 2 m-warps x 64 rows
    const int wn   = wid >> 1;           // 2 n-warps x 64 cols

    const int e    = blockIdx.z;
    const int row0 = blockIdx.y * 128;
    const int col0 = blockIdx.x * 128;

    const __half* A = Ag + (size_t)e * CAP * K + (size_t)row0 * K;
    const __half* B = Bg + (size_t)e * NTOT * K + (size_t)col0 * K;
    const float* bias = bias_g + (size_t)e * NTOT + col0;

    float acc[4][8][4];
#pragma unroll
    for (int mt = 0; mt < 4; mt++)
#pragma unroll
        for (int nt = 0; nt < 8; nt++)
#pragma unroll
            for (int q = 0; q < 4; q++) acc[mt][nt][q] = 0.f;

    // ldmatrix per-lane offsets (SW128, row-XOR form); mt/bt offsets are +2048B
    const uint32_t aRow  = (uint32_t)(wm * 64 + (lane & 15));
    const uint32_t aBase = aRow * 128 + (uint32_t)((lane >> 4) * 16);
    const uint32_t aMask = (aRow & 7u) << 4;
    const uint32_t bRow  = (uint32_t)(wn * 64 + ((lane >> 4) * 8) + (lane & 7));
    const uint32_t bBase = bRow * 128 + (uint32_t)(((lane >> 3) & 1) * 16);
    const uint32_t bMask = (bRow & 7u) << 4;

    // loader: 2048 x 16B segs per chunk = 16 per thread (8 A rows + 8 B rows)
    const uint32_t lr = (uint32_t)(tid >> 3);      // 0..15
    const uint32_t ls = (uint32_t)(tid & 7);       // 0..7
    const uint32_t sOff0 = swz(lr * 128 + ls * 16);
    const __half* gA0 = A + (size_t)lr * K + ls * 8;
    const __half* gB0 = B + (size_t)lr * K + ls * 8;

    auto prefetch = [&](int c, int stage) {
        const uint32_t sb = sbase + (uint32_t)stage * ST_SZ;
        const size_t ko = (size_t)c * 64;
#pragma unroll
        for (int q = 0; q < 8; q++) {
            cp_async16(sb + OFF_A + sOff0 + (uint32_t)(q * 2048), gA0 + (size_t)(q * 16) * K + ko);
            cp_async16(sb + OFF_B + sOff0 + (uint32_t)(q * 2048), gB0 + (size_t)(q * 16) * K + ko);
        }
    };

    uint32_t fa[2][4][4], fb[2][4][4];
    auto ldfrag = [&](int buf, uint32_t sb, int kk) {
        const uint32_t kByte = (uint32_t)(kk * 32);
#pragma unroll
        for (int mt = 0; mt < 4; mt++) {
            uint32_t ua = (sb + OFF_A + aBase + (uint32_t)(mt * 2048) + kByte) ^ aMask;
            LDSM4(fa[buf][mt][0], fa[buf][mt][1], fa[buf][mt][2], fa[buf][mt][3], ua);
        }
#pragma unroll
        for (int bt = 0; bt < 4; bt++) {
            uint32_t ub = (sb + OFF_B + bBase + (uint32_t)(bt * 2048) + kByte) ^ bMask;
            LDSM4(fb[buf][bt][0], fb[buf][bt][1], fb[buf][bt][2], fb[buf][bt][3], ub);
        }
    };

    const int NC = K / 64;
    prefetch(0, 0); CP_COMMIT();
    prefetch(1, 1); CP_COMMIT();

    for (int c = 0; c < NC; c++) {
        CP_WAIT1();                           // stage c%3 resident
        __syncthreads();                      // + all warps done reading stage (c-1)%3
        if (c + 2 < NC) prefetch(c + 2, (c + 2) % 3);
        CP_COMMIT();

        const uint32_t sb = sbase + (uint32_t)(c % 3) * ST_SZ;
        ldfrag(0, sb, 0);
#pragma unroll
        for (int kk = 0; kk < 4; kk++) {
            const int cur = kk & 1;
            if (kk < 3) ldfrag(cur ^ 1, sb, kk + 1);   // overlap next-k frag loads with MMAs
#pragma unroll
            for (int mt = 0; mt < 4; mt++)
#pragma unroll
                for (int bt = 0; bt < 4; bt++) {
                    uint32_t b0[2] = {fb[cur][bt][0], fb[cur][bt][1]};
                    uint32_t b1[2] = {fb[cur][bt][2], fb[cur][bt][3]};
                    mma16816(acc[mt][2 * bt + 0], fa[cur][mt], b0);
                    mma16816(acc[mt][2 * bt + 1], fa[cur][mt], b1);
                }
        }
    }

    // ---- epilogue ----
    const int lrow = lane >> 2;
    const int lcol = (lane & 3) * 2;
    if (MODE == 0) {
        const size_t orow0 = (size_t)e * CAP + row0;
#pragma unroll
        for (int mt = 0; mt < 4; mt++)
#pragma unroll
            for (int half = 0; half < 2; half++) {
                size_t grow = orow0 + wm * 64 + mt * 16 + half * 8 + lrow;
#pragma unroll
                for (int nt = 0; nt < 8; nt++) {
                    int bc = wn * 64 + nt * 8 + lcol;
                    float v0 = acc[mt][nt][half * 2 + 0] + bias[bc];
                    float v1 = acc[mt][nt][half * 2 + 1] + bias[bc + 1];
                    v0 = 0.5f * v0 * (1.0f + erff(v0 * 0.70710678118654752f));
                    v1 = 0.5f * v1 * (1.0f + erff(v1 * 0.70710678118654752f));
                    *(uint32_t*)(outh + grow * NTOT + col0 + bc) = pack_h2(v0, v1);
                }
            }
    } else {
        const int count = min(g_counts[e], CAP);
#pragma unroll
        for (int mt = 0; mt < 4; mt++)
#pragma unroll
            for (int half = 0; half < 2; half++) {
                int lrw = row0 + wm * 64 + mt * 16 + half * 8 + lrow;
                if (lrw < count) {
                    int n = g_tok_of_slot[e * CAP + lrw];
                    float scale = g_oscale[n];
                    float* orow = outf + (size_t)n * NTOT;
#pragma unroll
                    for (int nt = 0; nt < 8; nt++) {
                        int bc = wn * 64 + nt * 8 + lcol;
                        float v0 = (acc[mt][nt][half * 2 + 0] + bias[bc]) * scale;
                        float v1 = (acc[mt][nt][half * 2 + 1] + bias[bc + 1]) * scale;
                        *(float2*)(orow + col0 + bc) = make_float2(v0, v1);
                    }
                }
            }
    }
}

// ================= launch =================
extern "C" void kernel_launch(void* const* d_in, const int* in_sizes, int n_in,
                              void* d_out, int out_size) {
    const float* x  = (const float*)d_in[0];
    const float* Wg = (const float*)d_in[1];
    const float* W1 = (const float*)d_in[2];
    const float* b1 = (const float*)d_in[3];
    const float* W2 = (const float*)d_in[4];
    const float* b2 = (const float*)d_in[5];
    float* out = (float*)d_out;
    float* aux_out = (out_size > NTOK * DIM) ? (out + (size_t)NTOK * DIM) : nullptr;

    cudaFuncSetAttribute(gemm_kernel<0, DIM, HID>,
                         cudaFuncAttributeMaxDynamicSharedMemorySize, GEMM_SMEM);
    cudaFuncSetAttribute(gemm_kernel<1, HID, DIM>,
                         cudaFuncAttributeMaxDynamicSharedMemorySize, GEMM_SMEM);

    __half *w1f, *w2f, *xf, *hf;
    int* counts;
    cudaGetSymbolAddress((void**)&w1f, g_w1f);
    cudaGetSymbolAddress((void**)&w2f, g_w2f);
    cudaGetSymbolAddress((void**)&xf, g_xf);
    cudaGetSymbolAddress((void**)&hf, g_hf);
    cudaGetSymbolAddress((void**)&counts, g_counts);

    cudaMemsetAsync(out, 0, (size_t)out_size * sizeof(float), 0);
    cudaMemsetAsync(counts, 0, NEXP * sizeof(int), 0);

    prep_kernel<<<256 + 2 * 8192, 256>>>(x, Wg, W1, W2, w1f, w2f);
    pos_reduce_kernel<<<9, 1024>>>(aux_out);
    gather_kernel<<<NEXP * CAP + NTOK / 128, 128>>>(x);

    dim3 g1(HID / 128, CAP / 128, NEXP);   // 32 x 8 x 8
    gemm_kernel<0, DIM, HID><<<g1, 128, GEMM_SMEM>>>(xf, w1f, b1, hf, nullptr);

    dim3 g2(DIM / 128, CAP / 128, NEXP);   // 8 x 8 x 8
    gemm_kernel<1, HID, DIM><<<g2, 128, GEMM_SMEM>>>(hf, w2f, b2, nullptr, out);
}

// round 16
// speedup vs baseline: 1.0189x; 1.0189x over previous
#include <cuda_runtime.h>
#include <cuda_fp16.h>
#include <math.h>
#include <stdint.h>

#define NTOK 8192
#define DIM  1024
#define NEXP 8
#define HID  4096
#define CAP  1024

// ================= scratch =================
__device__ __half g_xf[(size_t)NTOK * DIM];
__device__ __half g_hf[(size_t)NTOK * HID];
__device__ __half g_w1f[(size_t)NEXP * HID * DIM];  // transposed [E][H][D]
__device__ __half g_w2f[(size_t)NEXP * DIM * HID];  // transposed [E][D][H]
__device__ float g_probs[(size_t)NTOK * NEXP];
__device__ float g_lse2[NTOK];
__device__ float g_eprob[NTOK];
__device__ float g_oscale[NTOK];
__device__ int   g_eidx[NTOK];
__device__ int   g_slot[NTOK];
__device__ int   g_sortidx[NTOK];
__device__ int   g_tok_of_slot[NEXP * CAP];
__device__ int   g_counts[NEXP];

__device__ __forceinline__ uint32_t smem_u32(const void* p) {
    uint32_t a;
    asm("{ .reg .u64 t; cvta.to.shared.u64 t, %1; cvt.u32.u64 %0, t; }" : "=r"(a) : "l"(p));
    return a;
}
__device__ __forceinline__ uint32_t pack_h2(float a, float b) {
    __half2 h = __floats2half2_rn(a, b);
    return *(uint32_t*)&h;
}

// ---- PTX: mma / ldmatrix / cp.async ----
__device__ __forceinline__ void mma16816(float* c, const uint32_t* a, const uint32_t* b) {
    asm volatile("mma.sync.aligned.m16n8k16.row.col.f32.f16.f16.f32 "
                 "{%0,%1,%2,%3}, {%4,%5,%6,%7}, {%8,%9}, {%0,%1,%2,%3};"
                 : "+f"(c[0]), "+f"(c[1]), "+f"(c[2]), "+f"(c[3])
                 : "r"(a[0]), "r"(a[1]), "r"(a[2]), "r"(a[3]), "r"(b[0]), "r"(b[1]));
}
#define LDSM4(r0, r1, r2, r3, a) \
    asm volatile("ldmatrix.sync.aligned.m8n8.x4.shared.b16 {%0,%1,%2,%3}, [%4];" \
                 : "=r"(r0), "=r"(r1), "=r"(r2), "=r"(r3) : "r"(a))
__device__ __forceinline__ void cp_async16(uint32_t saddr, const void* gptr) {
    asm volatile("cp.async.cg.shared.global [%0], [%1], 16;" :: "r"(saddr), "l"(gptr));
}
#define CP_COMMIT() asm volatile("cp.async.commit_group;" ::: "memory")
#define CP_WAIT1()  asm volatile("cp.async.wait_group 1;" ::: "memory")

__device__ __forceinline__ uint32_t swz(uint32_t off) { return off ^ ((off >> 3) & 0x70); }

// ================= router (grid 256, block 256) =================
__global__ __launch_bounds__(256) void router_kernel(
    const float* __restrict__ x, const float* __restrict__ Wg)
{
    __shared__ float sh[8192];
    const int bid = blockIdx.x;
    const int tid = threadIdx.x;
#pragma unroll
    for (int k = 0; k < 32; k++) {
        int j = k * 256 + tid;
        sh[(j & 7) * 1024 + (j >> 3)] = Wg[j];   // sWg[e][d]
    }
    __syncthreads();
    const int warp = tid >> 5, lane = tid & 31;
#pragma unroll 1
    for (int it = 0; it < 4; it++) {
        int n = bid * 32 + it * 8 + warp;
        const float* xr = x + (size_t)n * DIM;
        float acc[NEXP];
#pragma unroll
        for (int e = 0; e < NEXP; e++) acc[e] = 0.f;
#pragma unroll 8
        for (int i = 0; i < 32; i++) {
            int d = lane + i * 32;
            float xv = xr[d];
#pragma unroll
            for (int e = 0; e < NEXP; e++) acc[e] += xv * sh[e * 1024 + d];
        }
#pragma unroll
        for (int e = 0; e < NEXP; e++) {
#pragma unroll
            for (int o = 16; o > 0; o >>= 1)
                acc[e] += __shfl_xor_sync(0xffffffffu, acc[e], o);
        }
        if (lane == 0) {
            float m = acc[0]; int bi = 0;
#pragma unroll
            for (int e = 1; e < NEXP; e++) if (acc[e] > m) { m = acc[e]; bi = e; }
            float p[NEXP], s = 0.f;
#pragma unroll
            for (int e = 0; e < NEXP; e++) { p[e] = expf(acc[e] - m); s += p[e]; }
            float inv = 1.f / s;
#pragma unroll
            for (int e = 0; e < NEXP; e++) {
                p[e] *= inv;
                g_probs[(size_t)n * NEXP + e] = p[e];
            }
            float lse = m + logf(s);
            g_lse2[n] = lse * lse;
            g_eidx[n] = bi;
            g_eprob[n] = p[bi];
            atomicAdd(&g_counts[bi], 1);
        }
    }
}

// ================= weight transpose + fp16 convert (grid 8192) =================
// src [E][K][N] fp32 -> dst [E][N][K] fp16, 64x64 tiles
__global__ __launch_bounds__(256) void convert_kernel(
    const float* __restrict__ src, __half* __restrict__ dst, int K, int N)
{
    __shared__ float sh[64 * 65];
    const int tid = threadIdx.x;
    int b = blockIdx.x;
    int e = b >> 10;
    int rem = b & 1023;
    int tiles_n = N >> 6;
    int nx = rem % tiles_n, ky = rem / tiles_n;
    const float* s = src + (size_t)e * K * N;
    __half* o = dst + (size_t)e * N * K;
    int n0 = nx * 64, k0 = ky * 64;
#pragma unroll
    for (int i = 0; i < 16; i++) {
        int lin = i * 256 + tid;
        int kr = lin >> 6, nc = lin & 63;
        sh[kr * 65 + nc] = s[(size_t)(k0 + kr) * N + n0 + nc];
    }
    __syncthreads();
    int r = tid >> 2, c4 = tid & 3;
    uint32_t w[8];
#pragma unroll
    for (int j = 0; j < 8; j++) {
        float a = sh[(c4 * 16 + 2 * j) * 65 + r];
        float bb = sh[(c4 * 16 + 2 * j + 1) * 65 + r];
        w[j] = pack_h2(a, bb);
    }
    uint4* dp = (uint4*)(o + (size_t)(n0 + r) * K + k0 + c4 * 16);
    dp[0] = make_uint4(w[0], w[1], w[2], w[3]);
    dp[1] = make_uint4(w[4], w[5], w[6], w[7]);
}

// ================= fused pos (blocks 0..7) + reduce (block 8) =================
__global__ __launch_bounds__(1024) void pos_reduce_kernel(float* aux_out) {
    const int tid = threadIdx.x;
    if (blockIdx.x < 8) {
        const int e = blockIdx.x;
        const int lane = tid & 31, wid = tid >> 5;
        __shared__ int wsum[32], wbase[32], sbase;
        int st = 0;
        for (int j = 0; j < e; j++) st += g_counts[j];
        if (tid == 0) sbase = 0;
        __syncthreads();
        for (int n0 = 0; n0 < NTOK; n0 += 1024) {
            int n = n0 + tid;
            bool pred = (g_eidx[n] == e);
            unsigned b = __ballot_sync(0xffffffffu, pred);
            int wpre = __popc(b & ((1u << lane) - 1u));
            if (lane == 0) wsum[wid] = __popc(b);
            __syncthreads();
            if (tid == 0) {
                int r = sbase;
#pragma unroll
                for (int w = 0; w < 32; w++) { wbase[w] = r; r += wsum[w]; }
                sbase = r;
            }
            __syncthreads();
            if (pred) {
                int pos = wbase[wid] + wpre;
                g_sortidx[st + pos] = n;
                if (pos < CAP) { g_slot[n] = pos; g_tok_of_slot[e * CAP + pos] = n; }
                else g_slot[n] = -1;
            }
            __syncthreads();
        }
    } else {
        __shared__ float sz[1024];
        __shared__ float sp[NEXP][1024];
        float z = 0.f, p[NEXP];
#pragma unroll
        for (int e = 0; e < NEXP; e++) p[e] = 0.f;
        for (int n = tid; n < NTOK; n += 1024) {
            z += g_lse2[n];
#pragma unroll
            for (int e = 0; e < NEXP; e++) p[e] += g_probs[(size_t)n * NEXP + e];
        }
        sz[tid] = z;
#pragma unroll
        for (int e = 0; e < NEXP; e++) sp[e][tid] = p[e];
        __syncthreads();
        for (int off = 512; off > 0; off >>= 1) {
            if (tid < off) {
                sz[tid] += sz[tid + off];
#pragma unroll
                for (int e = 0; e < NEXP; e++) sp[e][tid] += sp[e][tid + off];
            }
            __syncthreads();
        }
        if (tid == 0) {
            float zloss = sz[0] / (float)NTOK;
            float dot = 0.f;
#pragma unroll
            for (int e = 0; e < NEXP; e++) {
                float fi = (float)g_counts[e] / (float)NTOK;
                float pi = sp[e][0] / (float)NTOK;
                dot += fi * pi;
            }
            if (aux_out) *aux_out = 0.01f * (float)NEXP * dot + 0.001f * zloss;
        }
    }
}

// ================= fused gather (blocks 0..8191) + oscale (8192..8255) =================
__global__ __launch_bounds__(128) void gather_kernel(const float* __restrict__ x) {
    int bid = blockIdx.x;
    if (bid < NEXP * CAP) {
        int e = bid >> 10;
        int slot = bid & (CAP - 1);
        if (slot >= min(g_counts[e], CAP)) return;
        int n = g_tok_of_slot[bid];
        const float4* src = (const float4*)(x + (size_t)n * DIM);
        uint2* dst = (uint2*)(g_xf + (size_t)bid * DIM);
#pragma unroll
        for (int q = 0; q < 2; q++) {
            int i = q * 128 + threadIdx.x;
            float4 v = src[i];
            dst[i] = make_uint2(pack_h2(v.x, v.y), pack_h2(v.z, v.w));
        }
    } else {
        int n = (bid - NEXP * CAP) * 128 + threadIdx.x;
        g_oscale[n] = g_eprob[g_sortidx[n]];
    }
}

// ====== fp16 HMMA grouped GEMM (R13 config): 128x128 tile, 256 thr, BK=64, 2 stages ======
#define OFF_A  0u
#define OFF_B  16384u
#define ST_SZ  32768u
#define GEMM_SMEM (2u * ST_SZ)

// MODE 0: GELU epilogue -> fp16 hidden; MODE 1: final -> out[token] * oscale
template <int MODE, int K, int NTOT>
__global__ __launch_bounds__(256, 2) void gemm_kernel(
    const __half* __restrict__ Ag, const __half* __restrict__ Bg,
    const float* __restrict__ bias_g,
    __half* __restrict__ outh, float* __restrict__ outf)
{
    extern __shared__ __align__(128) char smem[];
    const uint32_t sbase = smem_u32(smem);
    const int tid  = threadIdx.x;
    const int wid  = tid >> 5;
    const int lane = tid & 31;
    const int wm   = wid & 3;
    const int wn   = wid >> 2;

    const int e    = blockIdx.z;
    const int row0 = blockIdx.y * 128;
    const int col0 = blockIdx.x * 128;

    const __half* A = Ag + (size_t)e * CAP * K + (size_t)row0 * K;
    const __half* B = Bg + (size_t)e * NTOT * K + (size_t)col0 * K;
    const float* bias = bias_g + (size_t)e * NTOT + col0;

    float acc[2][8][4];
#pragma unroll
    for (int mt = 0; mt < 2; mt++)
#pragma unroll
        for (int nt = 0; nt < 8; nt++)
#pragma unroll
            for (int q = 0; q < 4; q++) acc[mt][nt][q] = 0.f;

    const uint32_t aRow  = (uint32_t)(wm * 32 + (lane & 15));
    const uint32_t aBase = aRow * 128 + (uint32_t)((lane >> 4) * 16);
    const uint32_t aMask = (aRow & 7u) << 4;
    const uint32_t bRow  = (uint32_t)(wn * 64 + ((lane >> 4) * 8) + (lane & 7));
    const uint32_t bBase = bRow * 128 + (uint32_t)(((lane >> 3) & 1) * 16);
    const uint32_t bMask = (bRow & 7u) << 4;

    const uint32_t lr = (uint32_t)(tid >> 3);      // 0..31
    const uint32_t ls = (uint32_t)(tid & 7);       // 0..7
    const uint32_t sOff0 = swz(lr * 128 + ls * 16);
    const __half* gA0 = A + (size_t)lr * K + ls * 8;
    const __half* gB0 = B + (size_t)lr * K + ls * 8;

    auto prefetch = [&](int c, int stage) {
        const uint32_t sb = sbase + (uint32_t)stage * ST_SZ;
        const size_t ko = (size_t)c * 64;
#pragma unroll
        for (int q = 0; q < 4; q++) {
            cp_async16(sb + OFF_A + sOff0 + (uint32_t)(q * 4096), gA0 + (size_t)(q * 32) * K + ko);
            cp_async16(sb + OFF_B + sOff0 + (uint32_t)(q * 4096), gB0 + (size_t)(q * 32) * K + ko);
        }
    };

    const int NC = K / 64;
    prefetch(0, 0); CP_COMMIT();

    for (int c = 0; c < NC; c++) {
        __syncthreads();                       // all warps done reading stage (c+1)&1
        if (c + 1 < NC) prefetch(c + 1, (c + 1) & 1);
        CP_COMMIT();
        CP_WAIT1();                            // stage c&1 resident
        __syncthreads();

        const uint32_t sb = sbase + (uint32_t)(c & 1) * ST_SZ;
#pragma unroll
        for (int kk = 0; kk < 4; kk++) {
            const uint32_t kByte = (uint32_t)(kk * 32);
            uint32_t af[2][4];
#pragma unroll
            for (int mt = 0; mt < 2; mt++) {
                uint32_t ua = (sb + OFF_A + aBase + (uint32_t)(mt * 2048) + kByte) ^ aMask;
                LDSM4(af[mt][0], af[mt][1], af[mt][2], af[mt][3], ua);
            }
#pragma unroll
            for (int bt = 0; bt < 4; bt++) {
                uint32_t ub = (sb + OFF_B + bBase + (uint32_t)(bt * 2048) + kByte) ^ bMask;
                uint32_t r0, r1, r2, r3;
                LDSM4(r0, r1, r2, r3, ub);
                uint32_t bf0[2] = {r0, r1}, bf1[2] = {r2, r3};
#pragma unroll
                for (int mt = 0; mt < 2; mt++) {
                    mma16816(acc[mt][2 * bt + 0], af[mt], bf0);
                    mma16816(acc[mt][2 * bt + 1], af[mt], bf1);
                }
            }
        }
    }

    // ---- epilogue ----
    const int lrow = lane >> 2;
    const int lcol = (lane & 3) * 2;
    if (MODE == 0) {
        const size_t orow0 = (size_t)e * CAP + row0;
#pragma unroll
        for (int mt = 0; mt < 2; mt++)
#pragma unroll
            for (int half = 0; half < 2; half++) {
                size_t grow = orow0 + wm * 32 + mt * 16 + half * 8 + lrow;
#pragma unroll
                for (int nt = 0; nt < 8; nt++) {
                    int bc = wn * 64 + nt * 8 + lcol;
                    float v0 = acc[mt][nt][half * 2 + 0] + bias[bc];
                    float v1 = acc[mt][nt][half * 2 + 1] + bias[bc + 1];
                    v0 = 0.5f * v0 * (1.0f + erff(v0 * 0.70710678118654752f));
                    v1 = 0.5f * v1 * (1.0f + erff(v1 * 0.70710678118654752f));
                    *(uint32_t*)(outh + grow * NTOT + col0 + bc) = pack_h2(v0, v1);
                }
            }
    } else {
        const int count = min(g_counts[e], CAP);
#pragma unroll
        for (int mt = 0; mt < 2; mt++)
#pragma unroll
            for (int half = 0; half < 2; half++) {
                int lrw = row0 + wm * 32 + mt * 16 + half * 8 + lrow;
                if (lrw < count) {
                    int n = g_tok_of_slot[e * CAP + lrw];
                    float scale = g_oscale[n];
                    float* orow = outf + (size_t)n * NTOT;
#pragma unroll
                    for (int nt = 0; nt < 8; nt++) {
                        int bc = wn * 64 + nt * 8 + lcol;
                        float v0 = (acc[mt][nt][half * 2 + 0] + bias[bc]) * scale;
                        float v1 = (acc[mt][nt][half * 2 + 1] + bias[bc + 1]) * scale;
                        *(float2*)(orow + col0 + bc) = make_float2(v0, v1);
                    }
                }
            }
    }
}

// ================= launch (graph fork-join: converts overlap router chain / GEMM1) =====
extern "C" void kernel_launch(void* const* d_in, const int* in_sizes, int n_in,
                              void* d_out, int out_size) {
    const float* x  = (const float*)d_in[0];
    const float* Wg = (const float*)d_in[1];
    const float* W1 = (const float*)d_in[2];
    const float* b1 = (const float*)d_in[3];
    const float* W2 = (const float*)d_in[4];
    const float* b2 = (const float*)d_in[5];
    float* out = (float*)d_out;
    float* aux_out = (out_size > NTOK * DIM) ? (out + (size_t)NTOK * DIM) : nullptr;

    cudaFuncSetAttribute(gemm_kernel<0, DIM, HID>,
                         cudaFuncAttributeMaxDynamicSharedMemorySize, GEMM_SMEM);
    cudaFuncSetAttribute(gemm_kernel<1, HID, DIM>,
                         cudaFuncAttributeMaxDynamicSharedMemorySize, GEMM_SMEM);

    __half *w1f, *w2f, *xf, *hf;
    int* counts;
    cudaGetSymbolAddress((void**)&w1f, g_w1f);
    cudaGetSymbolAddress((void**)&w2f, g_w2f);
    cudaGetSymbolAddress((void**)&xf, g_xf);
    cudaGetSymbolAddress((void**)&hf, g_hf);
    cudaGetSymbolAddress((void**)&counts, g_counts);

    // fork side streams off the capture stream (host-side ops: capture-time only)
    cudaStream_t sA, sB;
    cudaStreamCreateWithFlags(&sA, cudaStreamNonBlocking);
    cudaStreamCreateWithFlags(&sB, cudaStreamNonBlocking);
    cudaEvent_t evRoot, evA, evB;
    cudaEventCreateWithFlags(&evRoot, cudaEventDisableTiming);
    cudaEventCreateWithFlags(&evA, cudaEventDisableTiming);
    cudaEventCreateWithFlags(&evB, cudaEventDisableTiming);

    cudaEventRecord(evRoot, 0);
    cudaStreamWaitEvent(sA, evRoot, 0);
    cudaStreamWaitEvent(sB, evRoot, 0);

    // stream A: W1 convert (needed by GEMM1)
    convert_kernel<<<8192, 256, 0, sA>>>(W1, w1f, DIM, HID);
    cudaEventRecord(evA, sA);

    // stream B: out memset + W2 convert (needed by GEMM2)
    cudaMemsetAsync(out, 0, (size_t)out_size * sizeof(float), sB);
    convert_kernel<<<8192, 256, 0, sB>>>(W2, w2f, HID, DIM);
    cudaEventRecord(evB, sB);

    // main stream: router chain
    cudaMemsetAsync(counts, 0, NEXP * sizeof(int), 0);
    router_kernel<<<256, 256>>>(x, Wg);
    pos_reduce_kernel<<<9, 1024>>>(aux_out);
    gather_kernel<<<NEXP * CAP + NTOK / 128, 128>>>(x);

    cudaStreamWaitEvent(0, evA, 0);
    dim3 g1(HID / 128, CAP / 128, NEXP);   // 32 x 8 x 8
    gemm_kernel<0, DIM, HID><<<g1, 256, GEMM_SMEM>>>(xf, w1f, b1, hf, nullptr);

    cudaStreamWaitEvent(0, evB, 0);
    dim3 g2(DIM / 128, CAP / 128, NEXP);   // 8 x 8 x 8
    gemm_kernel<1, HID, DIM><<<g2, 256, GEMM_SMEM>>>(hf, w2f, b2, nullptr, out);

    cudaStreamDestroy(sA);
    cudaStreamDestroy(sB);
    cudaEventDestroy(evRoot);
    cudaEventDestroy(evA);
    cudaEventDestroy(evB);
}

// round 17
// speedup vs baseline: 1.0319x; 1.0128x over previous
#include <cuda_runtime.h>
#include <cuda_fp16.h>
#include <math.h>
#include <stdint.h>

#define NTOK 8192
#define DIM  1024
#define NEXP 8
#define HID  4096
#define CAP  1024

// ================= scratch =================
__device__ __half g_xf[(size_t)NTOK * DIM];
__device__ __half g_hf[(size_t)NTOK * HID];
__device__ __half g_w1f[(size_t)NEXP * HID * DIM];  // transposed [E][H][D]
__device__ __half g_w2f[(size_t)NEXP * DIM * HID];  // transposed [E][D][H]
__device__ float g_probs[(size_t)NTOK * NEXP];
__device__ float g_lse2[NTOK];
__device__ float g_eprob[NTOK];
__device__ float g_oscale[NTOK];
__device__ int   g_eidx[NTOK];
__device__ int   g_slot[NTOK];
__device__ int   g_sortidx[NTOK];
__device__ int   g_tok_of_slot[NEXP * CAP];
__device__ int   g_counts[NEXP];

__device__ __forceinline__ uint32_t smem_u32(const void* p) {
    uint32_t a;
    asm("{ .reg .u64 t; cvta.to.shared.u64 t, %1; cvt.u32.u64 %0, t; }" : "=r"(a) : "l"(p));
    return a;
}
__device__ __forceinline__ uint32_t pack_h2(float a, float b) {
    __half2 h = __floats2half2_rn(a, b);
    return *(uint32_t*)&h;
}

// ---- PTX: mma / ldmatrix / cp.async ----
__device__ __forceinline__ void mma16816(float* c, const uint32_t* a, const uint32_t* b) {
    asm volatile("mma.sync.aligned.m16n8k16.row.col.f32.f16.f16.f32 "
                 "{%0,%1,%2,%3}, {%4,%5,%6,%7}, {%8,%9}, {%0,%1,%2,%3};"
                 : "+f"(c[0]), "+f"(c[1]), "+f"(c[2]), "+f"(c[3])
                 : "r"(a[0]), "r"(a[1]), "r"(a[2]), "r"(a[3]), "r"(b[0]), "r"(b[1]));
}
#define LDSM4(r0, r1, r2, r3, a) \
    asm volatile("ldmatrix.sync.aligned.m8n8.x4.shared.b16 {%0,%1,%2,%3}, [%4];" \
                 : "=r"(r0), "=r"(r1), "=r"(r2), "=r"(r3) : "r"(a))
__device__ __forceinline__ void cp_async16(uint32_t saddr, const void* gptr) {
    asm volatile("cp.async.cg.shared.global [%0], [%1], 16;" :: "r"(saddr), "l"(gptr));
}
#define CP_COMMIT() asm volatile("cp.async.commit_group;" ::: "memory")
#define CP_WAIT1()  asm volatile("cp.async.wait_group 1;" ::: "memory")

__device__ __forceinline__ uint32_t swz(uint32_t off) { return off ^ ((off >> 3) & 0x70); }

// ================= router (grid 256, block 256) =================
__global__ __launch_bounds__(256) void router_kernel(
    const float* __restrict__ x, const float* __restrict__ Wg)
{
    __shared__ float sh[8192];
    const int bid = blockIdx.x;
    const int tid = threadIdx.x;
#pragma unroll
    for (int k = 0; k < 32; k++) {
        int j = k * 256 + tid;
        sh[(j & 7) * 1024 + (j >> 3)] = Wg[j];   // sWg[e][d]
    }
    __syncthreads();
    const int warp = tid >> 5, lane = tid & 31;
#pragma unroll 1
    for (int it = 0; it < 4; it++) {
        int n = bid * 32 + it * 8 + warp;
        const float* xr = x + (size_t)n * DIM;
        float acc[NEXP];
#pragma unroll
        for (int e = 0; e < NEXP; e++) acc[e] = 0.f;
#pragma unroll 8
        for (int i = 0; i < 32; i++) {
            int d = lane + i * 32;
            float xv = xr[d];
#pragma unroll
            for (int e = 0; e < NEXP; e++) acc[e] += xv * sh[e * 1024 + d];
        }
#pragma unroll
        for (int e = 0; e < NEXP; e++) {
#pragma unroll
            for (int o = 16; o > 0; o >>= 1)
                acc[e] += __shfl_xor_sync(0xffffffffu, acc[e], o);
        }
        if (lane == 0) {
            float m = acc[0]; int bi = 0;
#pragma unroll
            for (int e = 1; e < NEXP; e++) if (acc[e] > m) { m = acc[e]; bi = e; }
            float p[NEXP], s = 0.f;
#pragma unroll
            for (int e = 0; e < NEXP; e++) { p[e] = expf(acc[e] - m); s += p[e]; }
            float inv = 1.f / s;
#pragma unroll
            for (int e = 0; e < NEXP; e++) {
                p[e] *= inv;
                g_probs[(size_t)n * NEXP + e] = p[e];
            }
            float lse = m + logf(s);
            g_lse2[n] = lse * lse;
            g_eidx[n] = bi;
            g_eprob[n] = p[bi];
            atomicAdd(&g_counts[bi], 1);
        }
    }
}

// ================= weight transpose + fp16 convert (grid 8192) =================
__global__ __launch_bounds__(256) void convert_kernel(
    const float* __restrict__ src, __half* __restrict__ dst, int K, int N)
{
    __shared__ float sh[64 * 65];
    const int tid = threadIdx.x;
    int b = blockIdx.x;
    int e = b >> 10;
    int rem = b & 1023;
    int tiles_n = N >> 6;
    int nx = rem % tiles_n, ky = rem / tiles_n;
    const float* s = src + (size_t)e * K * N;
    __half* o = dst + (size_t)e * N * K;
    int n0 = nx * 64, k0 = ky * 64;
#pragma unroll
    for (int i = 0; i < 16; i++) {
        int lin = i * 256 + tid;
        int kr = lin >> 6, nc = lin & 63;
        sh[kr * 65 + nc] = s[(size_t)(k0 + kr) * N + n0 + nc];
    }
    __syncthreads();
    int r = tid >> 2, c4 = tid & 3;
    uint32_t w[8];
#pragma unroll
    for (int j = 0; j < 8; j++) {
        float a = sh[(c4 * 16 + 2 * j) * 65 + r];
        float bb = sh[(c4 * 16 + 2 * j + 1) * 65 + r];
        w[j] = pack_h2(a, bb);
    }
    uint4* dp = (uint4*)(o + (size_t)(n0 + r) * K + k0 + c4 * 16);
    dp[0] = make_uint4(w[0], w[1], w[2], w[3]);
    dp[1] = make_uint4(w[4], w[5], w[6], w[7]);
}

// ============ fused pos (blocks 0..7, 2 syncs) + reduce (block 8) ============
__global__ __launch_bounds__(1024) void pos_reduce_kernel(float* aux_out) {
    const int tid = threadIdx.x;
    if (blockIdx.x < 8) {
        const int e = blockIdx.x;
        const int lane = tid & 31, wid = tid >> 5;
        const unsigned lt = (1u << lane) - 1u;
        __shared__ int cnt[8][32];
        __shared__ int base[8][32];
        int st = 0;
#pragma unroll
        for (int j = 0; j < NEXP; j++) st += (j < e) ? g_counts[j] : 0;

        unsigned ball[8];
#pragma unroll
        for (int c = 0; c < 8; c++) {
            int n = c * 1024 + tid;
            bool pred = (g_eidx[n] == e);
            ball[c] = __ballot_sync(0xffffffffu, pred);
            if (lane == 0) cnt[c][wid] = __popc(ball[c]);
        }
        __syncthreads();
        if (tid == 0) {
            int run = 0;
#pragma unroll
            for (int c = 0; c < 8; c++)
#pragma unroll
                for (int w = 0; w < 32; w++) { base[c][w] = run; run += cnt[c][w]; }
        }
        __syncthreads();
#pragma unroll
        for (int c = 0; c < 8; c++) {
            if ((ball[c] >> lane) & 1u) {
                int pos = base[c][wid] + __popc(ball[c] & lt);
                int n = c * 1024 + tid;
                g_sortidx[st + pos] = n;
                if (pos < CAP) { g_slot[n] = pos; g_tok_of_slot[e * CAP + pos] = n; }
                else g_slot[n] = -1;
            }
        }
    } else {
        __shared__ float sz[1024];
        __shared__ float sp[NEXP][1024];
        float z = 0.f, p[NEXP];
#pragma unroll
        for (int e = 0; e < NEXP; e++) p[e] = 0.f;
        for (int n = tid; n < NTOK; n += 1024) {
            z += g_lse2[n];
#pragma unroll
            for (int e = 0; e < NEXP; e++) p[e] += g_probs[(size_t)n * NEXP + e];
        }
        sz[tid] = z;
#pragma unroll
        for (int e = 0; e < NEXP; e++) sp[e][tid] = p[e];
        __syncthreads();
        for (int off = 512; off > 0; off >>= 1) {
            if (tid < off) {
                sz[tid] += sz[tid + off];
#pragma unroll
                for (int e = 0; e < NEXP; e++) sp[e][tid] += sp[e][tid + off];
            }
            __syncthreads();
        }
        if (tid == 0) {
            float zloss = sz[0] / (float)NTOK;
            float dot = 0.f;
#pragma unroll
            for (int e = 0; e < NEXP; e++) {
                float fi = (float)g_counts[e] / (float)NTOK;
                float pi = sp[e][0] / (float)NTOK;
                dot += fi * pi;
            }
            if (aux_out) *aux_out = 0.01f * (float)NEXP * dot + 0.001f * zloss;
        }
    }
}

// ================= fused gather (blocks 0..8191) + oscale (8192..8255) =================
__global__ __launch_bounds__(128) void gather_kernel(const float* __restrict__ x) {
    int bid = blockIdx.x;
    if (bid < NEXP * CAP) {
        int e = bid >> 10;
        int slot = bid & (CAP - 1);
        if (slot >= min(g_counts[e], CAP)) return;
        int n = g_tok_of_slot[bid];
        const float4* src = (const float4*)(x + (size_t)n * DIM);
        uint2* dst = (uint2*)(g_xf + (size_t)bid * DIM);
#pragma unroll
        for (int q = 0; q < 2; q++) {
            int i = q * 128 + threadIdx.x;
            float4 v = src[i];
            dst[i] = make_uint2(pack_h2(v.x, v.y), pack_h2(v.z, v.w));
        }
    } else {
        int n = (bid - NEXP * CAP) * 128 + threadIdx.x;
        g_oscale[n] = g_eprob[g_sortidx[n]];
    }
}

// ====== fp16 HMMA grouped GEMM: 128x128 tile, 256 thr, BK=64, 2 stages ======
#define OFF_A  0u
#define OFF_B  16384u
#define ST_SZ  32768u
#define GEMM_SMEM (2u * ST_SZ)

// MODE 0: GELU epilogue -> fp16 hidden; MODE 1: final -> out[token] * oscale
template <int MODE, int K, int NTOT>
__global__ __launch_bounds__(256, 2) void gemm_kernel(
    const __half* __restrict__ Ag, const __half* __restrict__ Bg,
    const float* __restrict__ bias_g,
    __half* __restrict__ outh, float* __restrict__ outf, int eoff)
{
    extern __shared__ __align__(128) char smem[];
    const uint32_t sbase = smem_u32(smem);
    const int tid  = threadIdx.x;
    const int wid  = tid >> 5;
    const int lane = tid & 31;
    const int wm   = wid & 3;
    const int wn   = wid >> 2;

    const int e    = blockIdx.z + eoff;
    const int row0 = blockIdx.y * 128;
    const int col0 = blockIdx.x * 128;

    const __half* A = Ag + (size_t)e * CAP * K + (size_t)row0 * K;
    const __half* B = Bg + (size_t)e * NTOT * K + (size_t)col0 * K;
    const float* bias = bias_g + (size_t)e * NTOT + col0;

    float acc[2][8][4];
#pragma unroll
    for (int mt = 0; mt < 2; mt++)
#pragma unroll
        for (int nt = 0; nt < 8; nt++)
#pragma unroll
            for (int q = 0; q < 4; q++) acc[mt][nt][q] = 0.f;

    const uint32_t aRow  = (uint32_t)(wm * 32 + (lane & 15));
    const uint32_t aBase = aRow * 128 + (uint32_t)((lane >> 4) * 16);
    const uint32_t aMask = (aRow & 7u) << 4;
    const uint32_t bRow  = (uint32_t)(wn * 64 + ((lane >> 4) * 8) + (lane & 7));
    const uint32_t bBase = bRow * 128 + (uint32_t)(((lane >> 3) & 1) * 16);
    const uint32_t bMask = (bRow & 7u) << 4;

    const uint32_t lr = (uint32_t)(tid >> 3);      // 0..31
    const uint32_t ls = (uint32_t)(tid & 7);       // 0..7
    const uint32_t sOff0 = swz(lr * 128 + ls * 16);
    const __half* gA0 = A + (size_t)lr * K + ls * 8;
    const __half* gB0 = B + (size_t)lr * K + ls * 8;

    auto prefetch = [&](int c, int stage) {
        const uint32_t sb = sbase + (uint32_t)stage * ST_SZ;
        const size_t ko = (size_t)c * 64;
#pragma unroll
        for (int q = 0; q < 4; q++) {
            cp_async16(sb + OFF_A + sOff0 + (uint32_t)(q * 4096), gA0 + (size_t)(q * 32) * K + ko);
            cp_async16(sb + OFF_B + sOff0 + (uint32_t)(q * 4096), gB0 + (size_t)(q * 32) * K + ko);
        }
    };

    const int NC = K / 64;
    prefetch(0, 0); CP_COMMIT();

    for (int c = 0; c < NC; c++) {
        __syncthreads();
        if (c + 1 < NC) prefetch(c + 1, (c + 1) & 1);
        CP_COMMIT();
        CP_WAIT1();
        __syncthreads();

        const uint32_t sb = sbase + (uint32_t)(c & 1) * ST_SZ;
#pragma unroll
        for (int kk = 0; kk < 4; kk++) {
            const uint32_t kByte = (uint32_t)(kk * 32);
            uint32_t af[2][4];
#pragma unroll
            for (int mt = 0; mt < 2; mt++) {
                uint32_t ua = (sb + OFF_A + aBase + (uint32_t)(mt * 2048) + kByte) ^ aMask;
                LDSM4(af[mt][0], af[mt][1], af[mt][2], af[mt][3], ua);
            }
#pragma unroll
            for (int bt = 0; bt < 4; bt++) {
                uint32_t ub = (sb + OFF_B + bBase + (uint32_t)(bt * 2048) + kByte) ^ bMask;
                uint32_t r0, r1, r2, r3;
                LDSM4(r0, r1, r2, r3, ub);
                uint32_t bf0[2] = {r0, r1}, bf1[2] = {r2, r3};
#pragma unroll
                for (int mt = 0; mt < 2; mt++) {
                    mma16816(acc[mt][2 * bt + 0], af[mt], bf0);
                    mma16816(acc[mt][2 * bt + 1], af[mt], bf1);
                }
            }
        }
    }

    // ---- epilogue ----
    const int lrow = lane >> 2;
    const int lcol = (lane & 3) * 2;
    if (MODE == 0) {
        const size_t orow0 = (size_t)e * CAP + row0;
#pragma unroll
        for (int mt = 0; mt < 2; mt++)
#pragma unroll
            for (int half = 0; half < 2; half++) {
                size_t grow = orow0 + wm * 32 + mt * 16 + half * 8 + lrow;
#pragma unroll
                for (int nt = 0; nt < 8; nt++) {
                    int bc = wn * 64 + nt * 8 + lcol;
                    float v0 = acc[mt][nt][half * 2 + 0] + bias[bc];
                    float v1 = acc[mt][nt][half * 2 + 1] + bias[bc + 1];
                    v0 = 0.5f * v0 * (1.0f + erff(v0 * 0.70710678118654752f));
                    v1 = 0.5f * v1 * (1.0f + erff(v1 * 0.70710678118654752f));
                    *(uint32_t*)(outh + grow * NTOT + col0 + bc) = pack_h2(v0, v1);
                }
            }
    } else {
        const int count = min(g_counts[e], CAP);
#pragma unroll
        for (int mt = 0; mt < 2; mt++)
#pragma unroll
            for (int half = 0; half < 2; half++) {
                int lrw = row0 + wm * 32 + mt * 16 + half * 8 + lrow;
                if (lrw < count) {
                    int n = g_tok_of_slot[e * CAP + lrw];
                    float scale = g_oscale[n];
                    float* orow = outf + (size_t)n * NTOT;
#pragma unroll
                    for (int nt = 0; nt < 8; nt++) {
                        int bc = wn * 64 + nt * 8 + lcol;
                        float v0 = (acc[mt][nt][half * 2 + 0] + bias[bc]) * scale;
                        float v1 = (acc[mt][nt][half * 2 + 1] + bias[bc + 1]) * scale;
                        *(float2*)(orow + col0 + bc) = make_float2(v0, v1);
                    }
                }
            }
    }
}

// ================= launch (fork-join DAG with expert-halved GEMM pipelining) ==========
extern "C" void kernel_launch(void* const* d_in, const int* in_sizes, int n_in,
                              void* d_out, int out_size) {
    const float* x  = (const float*)d_in[0];
    const float* Wg = (const float*)d_in[1];
    const float* W1 = (const float*)d_in[2];
    const float* b1 = (const float*)d_in[3];
    const float* W2 = (const float*)d_in[4];
    const float* b2 = (const float*)d_in[5];
    float* out = (float*)d_out;
    float* aux_out = (out_size > NTOK * DIM) ? (out + (size_t)NTOK * DIM) : nullptr;

    cudaFuncSetAttribute(gemm_kernel<0, DIM, HID>,
                         cudaFuncAttributeMaxDynamicSharedMemorySize, GEMM_SMEM);
    cudaFuncSetAttribute(gemm_kernel<1, HID, DIM>,
                         cudaFuncAttributeMaxDynamicSharedMemorySize, GEMM_SMEM);

    __half *w1f, *w2f, *xf, *hf;
    int* counts;
    cudaGetSymbolAddress((void**)&w1f, g_w1f);
    cudaGetSymbolAddress((void**)&w2f, g_w2f);
    cudaGetSymbolAddress((void**)&xf, g_xf);
    cudaGetSymbolAddress((void**)&hf, g_hf);
    cudaGetSymbolAddress((void**)&counts, g_counts);

    // low-priority side streams (router wins SM arbitration at the front)
    int prLow = 0, prHigh = 0;
    cudaDeviceGetStreamPriorityRange(&prLow, &prHigh);   // prLow = numerically largest
    cudaStream_t sA, sB;
    cudaStreamCreateWithPriority(&sA, cudaStreamNonBlocking, prLow);
    cudaStreamCreateWithPriority(&sB, cudaStreamNonBlocking, prLow);
    cudaEvent_t evRoot, evA, evW2, ev1, evB2;
    cudaEventCreateWithFlags(&evRoot, cudaEventDisableTiming);
    cudaEventCreateWithFlags(&evA, cudaEventDisableTiming);
    cudaEventCreateWithFlags(&evW2, cudaEventDisableTiming);
    cudaEventCreateWithFlags(&ev1, cudaEventDisableTiming);
    cudaEventCreateWithFlags(&evB2, cudaEventDisableTiming);

    cudaEventRecord(evRoot, 0);
    cudaStreamWaitEvent(sA, evRoot, 0);
    cudaStreamWaitEvent(sB, evRoot, 0);

    // stream A: W1 convert (GEMM1 dependency)
    convert_kernel<<<8192, 256, 0, sA>>>(W1, w1f, DIM, HID);
    cudaEventRecord(evA, sA);

    // stream B: out memset + W2 convert (GEMM2 dependency)
    cudaMemsetAsync(out, 0, (size_t)out_size * sizeof(float), sB);
    convert_kernel<<<8192, 256, 0, sB>>>(W2, w2f, HID, DIM);
    cudaEventRecord(evW2, sB);

    // main stream: router chain
    cudaMemsetAsync(counts, 0, NEXP * sizeof(int), 0);
    router_kernel<<<256, 256>>>(x, Wg);
    pos_reduce_kernel<<<9, 1024>>>(aux_out);
    gather_kernel<<<NEXP * CAP + NTOK / 128, 128>>>(x);

    // GEMM1 experts 0..3, then 4..7 (main). GEMM2 0..3 overlaps GEMM1 4..7 (stream B).
    cudaStreamWaitEvent(0, evA, 0);
    dim3 gh1(HID / 128, CAP / 128, 4);     // 32 x 8 x 4
    gemm_kernel<0, DIM, HID><<<gh1, 256, GEMM_SMEM>>>(xf, w1f, b1, hf, nullptr, 0);
    cudaEventRecord(ev1, 0);
    gemm_kernel<0, DIM, HID><<<gh1, 256, GEMM_SMEM>>>(xf, w1f, b1, hf, nullptr, 4);

    dim3 gh2(DIM / 128, CAP / 128, 4);     // 8 x 8 x 4
    cudaStreamWaitEvent(sB, ev1, 0);       // hidden[0..3] ready (and dispatch data)
    gemm_kernel<1, HID, DIM><<<gh2, 256, GEMM_SMEM, sB>>>(hf, w2f, b2, nullptr, out, 0);
    cudaEventRecord(evB2, sB);

    cudaStreamWaitEvent(0, evW2, 0);       // W2 converted (ordering for main-half)
    gemm_kernel<1, HID, DIM><<<gh2, 256, GEMM_SMEM>>>(hf, w2f, b2, nullptr, out, 4);
    cudaStreamWaitEvent(0, evB2, 0);       // join stream B before harness reads out

    cudaStreamDestroy(sA);
    cudaStreamDestroy(sB);
    cudaEventDestroy(evRoot);
    cudaEventDestroy(evA);
    cudaEventDestroy(evW2);
    cudaEventDestroy(ev1);
    cudaEventDestroy(evB2);
}